// round 6
// baseline (speedup 1.0000x reference)
#include <cuda_runtime.h>
#include <cstdint>

#define NX 16384
#define NS 4096
#define DD 256

#define TMC 128             // CTA tile M
#define TNC 128             // CTA tile N
#define MTILES (NX / TMC)   // 128
#define NTILES_TOT (MTILES * (NS / TNC))  // 4096
#define BK 128              // fp8 elems per stage = one 128B row
#define A_STAGE (TMC * 128) // 16 KB
#define B_STAGE (TNC * 128) // 16 KB
#define STAGE (A_STAGE + B_STAGE)  // 32 KB
#define DYN_SMEM (3 * STAGE)       // 98304 -> 2 CTAs/SM

#define L2E 1.4426950408889634f
#define C2L2E 2.8853900817779268f  // 2*log2(e)

// Scratch (device globals; no allocation allowed)
__device__ __align__(16) uint8_t g_x8[NX * DD];  // e4m3
__device__ __align__(16) uint8_t g_s8[NS * DD];  // e4m3
__device__ float g_xls[NX];  // -||x||^2 * log2(e)
__device__ float g_sls[NS];  // -||s||^2 * log2(e)

// ---------------------------------------------------------------------------
// Prep: fp32 -> e4m3 + pre-scaled row norms (norms from exact fp32 values).
// One warp per row; lane converts 8 floats -> 8 bytes.
// ---------------------------------------------------------------------------
__device__ __forceinline__ uint16_t f2e4m3x2(float hi, float lo) {
    uint16_t r;
    asm("cvt.rn.satfinite.e4m3x2.f32 %0, %1, %2;" : "=h"(r) : "f"(hi), "f"(lo));
    return r;
}

__global__ void prep_kernel(const float* __restrict__ x,
                            const float* __restrict__ s) {
    int warp = (blockIdx.x * blockDim.x + threadIdx.x) >> 5;
    int lane = threadIdx.x & 31;
    if (warp >= NX + NS) return;
    const float* src;
    uint8_t* dst;
    float* sqout;
    if (warp < NX) {
        src = x + (size_t)warp * DD; dst = g_x8 + (size_t)warp * DD; sqout = g_xls + warp;
    } else {
        int r = warp - NX;
        src = s + (size_t)r * DD; dst = g_s8 + (size_t)r * DD; sqout = g_sls + r;
    }
    float4 v0 = reinterpret_cast<const float4*>(src)[lane * 2];
    float4 v1 = reinterpret_cast<const float4*>(src)[lane * 2 + 1];
    uint16_t h0 = f2e4m3x2(v0.y, v0.x);
    uint16_t h1 = f2e4m3x2(v0.w, v0.z);
    uint16_t h2 = f2e4m3x2(v1.y, v1.x);
    uint16_t h3 = f2e4m3x2(v1.w, v1.z);
    uint2 pk;
    pk.x = (uint32_t)h0 | ((uint32_t)h1 << 16);
    pk.y = (uint32_t)h2 | ((uint32_t)h3 << 16);
    reinterpret_cast<uint2*>(dst)[lane] = pk;
    float p = v0.x * v0.x + v0.y * v0.y + v0.z * v0.z + v0.w * v0.w +
              v1.x * v1.x + v1.y * v1.y + v1.z * v1.z + v1.w * v1.w;
#pragma unroll
    for (int o = 16; o; o >>= 1) p += __shfl_xor_sync(0xffffffffu, p, o);
    if (lane == 0) *sqout = -p * L2E;
}

// ---------------------------------------------------------------------------
__device__ __forceinline__ uint32_t cvta_s(const void* p) {
    uint32_t a;
    asm("{ .reg .u64 t; cvta.to.shared.u64 t, %1; cvt.u32.u64 %0, t; }"
        : "=r"(a) : "l"(p));
    return a;
}
__device__ __forceinline__ void cp16(uint32_t d, const void* s) {
    asm volatile("cp.async.cg.shared.global [%0], [%1], 16;\n" :: "r"(d), "l"(s));
}
__device__ __forceinline__ void ldsm_x4(uint32_t* r, uint32_t a) {
    asm volatile("ldmatrix.sync.aligned.m8n8.x4.shared.b16 {%0,%1,%2,%3}, [%4];"
                 : "=r"(r[0]), "=r"(r[1]), "=r"(r[2]), "=r"(r[3]) : "r"(a));
}
// FP8 e4m3 MMA, f32 accumulate: m16n8k32
__device__ __forceinline__ void mma_fp8(float* c, const uint32_t* a,
                                        uint32_t b0, uint32_t b1) {
    asm volatile(
        "mma.sync.aligned.m16n8k32.row.col.f32.e4m3.e4m3.f32 "
        "{%0,%1,%2,%3}, {%4,%5,%6,%7}, {%8,%9}, {%0,%1,%2,%3};\n"
        : "+f"(c[0]), "+f"(c[1]), "+f"(c[2]), "+f"(c[3])
        : "r"(a[0]), "r"(a[1]), "r"(a[2]), "r"(a[3]), "r"(b0), "r"(b1));
}
__device__ __forceinline__ float ex2(float w) {
    float r;
    asm("ex2.approx.f32 %0, %1;" : "=f"(r) : "f"(w));
    return r;
}

// B row permutation (as R5): smem row for global col gc so thread t4 of an
// nt pair owns 4 consecutive global columns -> float4 epilogue stores.
__device__ __forceinline__ int bperm(int gc) {
    int k = gc >> 4, w = gc & 15;
    int t4 = w >> 2, r = w & 3;
    return 16 * k + 8 * (r >> 1) + 2 * t4 + (r & 1);
}

// Load stage g (tile j = g/2, K-half g%2). Always commits a group.
__device__ __forceinline__ void load_stage(uint32_t sbase, int g,
                                           int ntiles_cta, int bid, int stride,
                                           int tid) {
    int j = g >> 1;
    if (j < ntiles_cta) {
        int T = bid + j * stride;
        int mB = (T & (MTILES - 1)) * TMC;
        int nB = (T >> 7) * TNC;
        int kb = (g & 1) * 128;  // byte offset of K-half within 256B row
        const char* aS = (const char*)g_x8 + (size_t)mB * 256 + kb;
        const char* bS = (const char*)g_s8 + (size_t)nB * 256 + kb;
        int r0 = tid >> 3;  // 0..15
        int jg = tid & 7;   // 16B granule in 128B row
#pragma unroll
        for (int i = 0; i < 8; i++) {  // A: 128 rows
            int row = r0 + 16 * i;
            uint32_t sw = (uint32_t)((jg ^ (row & 7)) * 16);
            cp16(sbase + row * 128 + sw, aS + (size_t)row * 256 + jg * 16);
        }
#pragma unroll
        for (int i = 0; i < 8; i++) {  // B: 128 rows, permuted destination
            int gc = r0 + 16 * i;
            int nb = bperm(gc);
            uint32_t sw = (uint32_t)((jg ^ (nb & 7)) * 16);
            cp16(sbase + A_STAGE + nb * 128 + sw,
                 bS + (size_t)gc * 256 + jg * 16);
        }
    }
    asm volatile("cp.async.commit_group;\n");
}

__global__ void __launch_bounds__(128, 2)
rbf_fp8_kernel(float* __restrict__ out) {
    extern __shared__ __align__(128) char dsm[];
    const int tid = threadIdx.x;
    const int lane = tid & 31;
    const int wid = tid >> 5;
    const int warpM = wid & 1;   // 2 warps along M (64 rows each)
    const int warpN = wid >> 1;  // 2 warps along N (64 cols each)
    const int bid = blockIdx.x;
    const int stride = gridDim.x;
    const int ntiles_cta = (NTILES_TOT - bid + stride - 1) / stride;

    const uint32_t s0 = cvta_s(dsm);
    const int swz = lane & 7;
    const int hi = lane >> 4;
    const uint32_t aRowOff = (uint32_t)(warpM * 64 + (lane & 15)) * 128;
    const uint32_t bRowOff =
        A_STAGE + (uint32_t)(warpN * 64 + (lane & 15)) * 128;

    float acc[4][8][4];
#pragma unroll
    for (int mt = 0; mt < 4; mt++)
#pragma unroll
        for (int nt = 0; nt < 8; nt++)
#pragma unroll
            for (int k = 0; k < 4; k++) acc[mt][nt][k] = 0.f;

    load_stage(s0, 0, ntiles_cta, bid, stride, tid);
    load_stage(s0 + STAGE, 1, ntiles_cta, bid, stride, tid);

    int g = 0;
    for (int j = 0; j < ntiles_cta; j++) {
        const int T = bid + j * stride;
        const int mB = (T & (MTILES - 1)) * TMC;
        const int nB = (T >> 7) * TNC;

#pragma unroll
        for (int half = 0; half < 2; half++, g++) {
            asm volatile("cp.async.wait_group 1;\n");
            __syncthreads();
            // Ring slot (g+2)%3 is free (held stage g-1, fully consumed).
            load_stage(s0 + (uint32_t)((g + 2) % 3) * STAGE, g + 2, ntiles_cta,
                       bid, stride, tid);
            const uint32_t sb = s0 + (uint32_t)(g % 3) * STAGE;
#pragma unroll
            for (int ks = 0; ks < 4; ks++) {  // 4 k32 steps per 128B stage
                const uint32_t csel = (uint32_t)(((ks * 2 + hi) ^ swz) * 16);
                uint32_t a[4][4];
#pragma unroll
                for (int mt = 0; mt < 4; mt++)
                    ldsm_x4(a[mt], sb + aRowOff + mt * (16 * 128) + csel);
#pragma unroll
                for (int bt = 0; bt < 4; bt++) {
                    uint32_t bb[4];
                    ldsm_x4(bb, sb + bRowOff + bt * (16 * 128) + csel);
#pragma unroll
                    for (int mt = 0; mt < 4; mt++) {
                        mma_fp8(acc[mt][bt * 2 + 0], a[mt], bb[0], bb[2]);
                        mma_fp8(acc[mt][bt * 2 + 1], a[mt], bb[1], bb[3]);
                    }
                }
            }
        }

        // Epilogue: out = min(2^(2*log2e*dot + xls + sls), 1). Registers +
        // global only; tile j+1's two stages are in flight underneath.
        {
            const int g8 = lane >> 2;
            const int t4 = lane & 3;
            const int colF = nB + warpN * 64 + t4 * 4;
            float4 ss4[4];
#pragma unroll
            for (int k = 0; k < 4; k++)
                ss4[k] = *reinterpret_cast<const float4*>(g_sls + colF + 16 * k);
#pragma unroll
            for (int mt = 0; mt < 4; mt++) {
                const int r0 = mB + warpM * 64 + mt * 16 + g8;
                const float xl0 = g_xls[r0];
                const float xl1 = g_xls[r0 + 8];
                float* o0 = out + (size_t)r0 * NS + colF;
                float* o1 = o0 + (size_t)8 * NS;
#pragma unroll
                for (int k = 0; k < 4; k++) {
                    float* e0 = acc[mt][2 * k];
                    float* e1 = acc[mt][2 * k + 1];
                    float4 v0, v1;
                    v0.x = fminf(ex2(fmaf(e0[0], C2L2E, xl0 + ss4[k].x)), 1.f);
                    v0.y = fminf(ex2(fmaf(e0[1], C2L2E, xl0 + ss4[k].y)), 1.f);
                    v0.z = fminf(ex2(fmaf(e1[0], C2L2E, xl0 + ss4[k].z)), 1.f);
                    v0.w = fminf(ex2(fmaf(e1[1], C2L2E, xl0 + ss4[k].w)), 1.f);
                    v1.x = fminf(ex2(fmaf(e0[2], C2L2E, xl1 + ss4[k].x)), 1.f);
                    v1.y = fminf(ex2(fmaf(e0[3], C2L2E, xl1 + ss4[k].y)), 1.f);
                    v1.z = fminf(ex2(fmaf(e1[2], C2L2E, xl1 + ss4[k].z)), 1.f);
                    v1.w = fminf(ex2(fmaf(e1[3], C2L2E, xl1 + ss4[k].w)), 1.f);
                    *reinterpret_cast<float4*>(o0 + 16 * k) = v0;
                    *reinterpret_cast<float4*>(o1 + 16 * k) = v1;
                    e0[0] = 0.f; e0[1] = 0.f; e0[2] = 0.f; e0[3] = 0.f;
                    e1[0] = 0.f; e1[1] = 0.f; e1[2] = 0.f; e1[3] = 0.f;
                }
            }
        }
    }
}

// ---------------------------------------------------------------------------
extern "C" void kernel_launch(void* const* d_in, const int* in_sizes, int n_in,
                              void* d_out, int out_size) {
    const float* x = (const float*)d_in[0];
    const float* s = (const float*)d_in[1];
    if (n_in >= 2 && in_sizes[0] < in_sizes[1]) {
        x = (const float*)d_in[1];
        s = (const float*)d_in[0];
    }
    float* out = (float*)d_out;

    static int nsm = 0;
    if (nsm == 0) {
        cudaFuncSetAttribute(rbf_fp8_kernel,
                             cudaFuncAttributeMaxDynamicSharedMemorySize,
                             DYN_SMEM);
        cudaDeviceGetAttribute(&nsm, cudaDevAttrMultiProcessorCount, 0);
        if (nsm <= 0) nsm = 148;
    }

    prep_kernel<<<(NX + NS) / 8, 256>>>(x, s);
    rbf_fp8_kernel<<<2 * nsm, 128, DYN_SMEM>>>(out);
}

// round 7
// speedup vs baseline: 1.1863x; 1.1863x over previous
#include <cuda_runtime.h>
#include <cuda_fp16.h>
#include <cstdint>

#define NX 16384
#define NS 4096
#define DD 256

#define TM 256              // CTA tile M
#define TN 128              // CTA tile N
#define MTILES (NX / TM)    // 64
#define NTILES_TOT ((NX / TM) * (NS / TN))  // 2048
#define BK 64               // K per stage (64 f16 = 128B rows)
#define A_STAGE (TM * 128)  // 32 KB
#define B_STAGE (TN * 128)  // 16 KB
#define STAGE (A_STAGE + B_STAGE)  // 48 KB
#define DYN_SMEM (2 * STAGE)       // 98304 -> 2 CTAs/SM

#define L2E 1.4426950408889634
// Schraudolph-folded constants: out = int_as_float(max((int)t, 0)),
// t = dot * K1 + (XLS + SLS), K1 = 2*log2(e)*2^23,
// XLS = 2^23*(127 - ||x||^2*log2e), SLS = -2^23*||s||^2*log2e.
#define K1F ((float)(2.0 * L2E * 8388608.0))

// Scratch (device globals; no allocation allowed)
__device__ __align__(16) __half g_xh[NX * DD];
__device__ __align__(16) __half g_sh[NS * DD];
__device__ float g_xls[NX];  // bias - ||x||^2 * log2e * 2^23
__device__ float g_sls[NS];  // -||s||^2 * log2e * 2^23

// ---------------------------------------------------------------------------
// Prep: fp32 -> fp16 + pre-scaled row norms. One warp per row.
// ---------------------------------------------------------------------------
__global__ void prep_kernel(const float* __restrict__ x,
                            const float* __restrict__ s) {
    int warp = (blockIdx.x * blockDim.x + threadIdx.x) >> 5;
    int lane = threadIdx.x & 31;
    if (warp >= NX + NS) return;
    const float* src;
    __half* dst;
    float* sqout;
    float bias;
    if (warp < NX) {
        src = x + (size_t)warp * DD; dst = g_xh + (size_t)warp * DD;
        sqout = g_xls + warp; bias = 1065353216.0f;  // 127 << 23
    } else {
        int r = warp - NX;
        src = s + (size_t)r * DD; dst = g_sh + (size_t)r * DD;
        sqout = g_sls + r; bias = 0.0f;
    }
    float4 v0 = reinterpret_cast<const float4*>(src)[lane * 2];
    float4 v1 = reinterpret_cast<const float4*>(src)[lane * 2 + 1];
    __half2 p0 = __floats2half2_rn(v0.x, v0.y);
    __half2 p1 = __floats2half2_rn(v0.z, v0.w);
    __half2 p2 = __floats2half2_rn(v1.x, v1.y);
    __half2 p3 = __floats2half2_rn(v1.z, v1.w);
    uint4 pk;
    pk.x = *reinterpret_cast<uint32_t*>(&p0);
    pk.y = *reinterpret_cast<uint32_t*>(&p1);
    pk.z = *reinterpret_cast<uint32_t*>(&p2);
    pk.w = *reinterpret_cast<uint32_t*>(&p3);
    reinterpret_cast<uint4*>(dst)[lane] = pk;
    float p = v0.x * v0.x + v0.y * v0.y + v0.z * v0.z + v0.w * v0.w +
              v1.x * v1.x + v1.y * v1.y + v1.z * v1.z + v1.w * v1.w;
#pragma unroll
    for (int o = 16; o; o >>= 1) p += __shfl_xor_sync(0xffffffffu, p, o);
    if (lane == 0) *sqout = fmaf(p, (float)(-L2E * 8388608.0), bias);
}

// ---------------------------------------------------------------------------
__device__ __forceinline__ uint32_t cvta_s(const void* p) {
    uint32_t a;
    asm("{ .reg .u64 t; cvta.to.shared.u64 t, %1; cvt.u32.u64 %0, t; }"
        : "=r"(a) : "l"(p));
    return a;
}
__device__ __forceinline__ void cp16(uint32_t d, const void* s) {
    asm volatile("cp.async.cg.shared.global [%0], [%1], 16;\n" :: "r"(d), "l"(s));
}
__device__ __forceinline__ void ldsm_x4(uint32_t* r, uint32_t a) {
    asm volatile("ldmatrix.sync.aligned.m8n8.x4.shared.b16 {%0,%1,%2,%3}, [%4];"
                 : "=r"(r[0]), "=r"(r[1]), "=r"(r[2]), "=r"(r[3]) : "r"(a));
}
__device__ __forceinline__ void mma_f16(uint32_t* c, const uint32_t* a,
                                        uint32_t b0, uint32_t b1) {
    asm volatile(
        "mma.sync.aligned.m16n8k16.row.col.f16.f16.f16.f16 "
        "{%0,%1}, {%2,%3,%4,%5}, {%6,%7}, {%0,%1};\n"
        : "+r"(c[0]), "+r"(c[1])
        : "r"(a[0]), "r"(a[1]), "r"(a[2]), "r"(a[3]), "r"(b0), "r"(b1));
}
// exp(-max(sq,0)) via exponent-bit construction, FMA/ALU pipes only.
// t already includes the exponent bias; (int)t saturates, max clamps to +0.0f.
__device__ __forceinline__ float fast_exp_bits(float dot, float xsls) {
    float t = fmaf(dot, K1F, xsls);
    int i = (int)t;               // cvt.rzi.s32.f32 (saturating)
    i = i > 0 ? i : 0;            // IMNMX
    return __int_as_float(i);
}

// B row permutation: smem row for global col gc so thread t4 of an nt pair
// owns 4 consecutive global columns -> float4 epilogue stores.
__device__ __forceinline__ int bperm(int gc) {
    int k = gc >> 4, w = gc & 15;
    int t4 = w >> 2, r = w & 3;
    return 16 * k + 8 * (r >> 1) + 2 * t4 + (r & 1);
}

// Load stage for global chunk g (tile j = g/4, k-chunk g%4). Always commits.
__device__ __forceinline__ void load_stage(uint32_t sbase, int g,
                                           int ntiles_cta, int bid, int stride,
                                           int tid) {
    int j = g >> 2;
    if (j < ntiles_cta) {
        int T = bid + j * stride;
        int mB = (T & (MTILES - 1)) * TM;
        int nB = (T >> 6) * TN;
        int kb = (g & 3) * 128;  // byte offset of K-chunk within 512B row
        const char* aS = (const char*)g_xh + (size_t)mB * 512 + kb;
        const char* bS = (const char*)g_sh + (size_t)nB * 512 + kb;
        int r0 = tid >> 3;       // 0..31
        int jg = tid & 7;        // 16B granule within 128B row
        size_t goff = (size_t)r0 * 512 + jg * 16;
        uint32_t aoff = sbase + r0 * 128 + (uint32_t)((jg ^ (r0 & 7)) * 16);
#pragma unroll
        for (int i = 0; i < 8; i++)  // A: 256 rows
            cp16(aoff + i * (32 * 128), aS + goff + (size_t)i * (32 * 512));
#pragma unroll
        for (int i = 0; i < 4; i++) {  // B: 128 rows, permuted destination
            int gc = r0 + 32 * i;
            int nb = bperm(gc);
            uint32_t boff =
                sbase + A_STAGE + nb * 128 + (uint32_t)((jg ^ (nb & 7)) * 16);
            cp16(boff, bS + (size_t)gc * 512 + jg * 16);
        }
    }
    asm volatile("cp.async.commit_group;\n");
}

__global__ void __launch_bounds__(256, 2)
rbf_f16_kernel(float* __restrict__ out) {
    extern __shared__ __align__(128) char dsm[];
    const int tid = threadIdx.x;
    const int lane = tid & 31;
    const int wid = tid >> 5;
    const int warpM = wid & 3;   // 4 warps along M (64 rows each)
    const int warpN = wid >> 2;  // 2 warps along N (64 cols each)
    const int bid = blockIdx.x;
    const int stride = gridDim.x;
    const int ntiles_cta = (NTILES_TOT - bid + stride - 1) / stride;
    if (ntiles_cta <= 0) return;

    const uint32_t s0 = cvta_s(dsm);
    const int swz = lane & 7;
    const int hi = lane >> 4;
    const uint32_t aRowOff = (uint32_t)(warpM * 64 + (lane & 15)) * 128;
    const uint32_t bRowOff =
        A_STAGE + (uint32_t)(warpN * 64 + (lane & 15)) * 128;

    uint32_t acc[4][8][2];
#pragma unroll
    for (int mt = 0; mt < 4; mt++)
#pragma unroll
        for (int nt = 0; nt < 8; nt++) {
            acc[mt][nt][0] = 0u; acc[mt][nt][1] = 0u;
        }

    load_stage(s0, 0, ntiles_cta, bid, stride, tid);
    load_stage(s0 + STAGE, 1, ntiles_cta, bid, stride, tid);

    int g = 0;
    for (int j = 0; j < ntiles_cta; j++) {
        const int T = bid + j * stride;
        const int mB = (T & (MTILES - 1)) * TM;
        const int nB = (T >> 6) * TN;

#pragma unroll
        for (int c4 = 0; c4 < 4; c4++, g++) {
            asm volatile("cp.async.wait_group 1;\n");
            __syncthreads();
            const uint32_t sb = s0 + (uint32_t)(g & 1) * STAGE;
#pragma unroll
            for (int ks = 0; ks < 4; ks++) {
                const uint32_t csel = (uint32_t)(((ks * 2 + hi) ^ swz) * 16);
                uint32_t a[4][4];
#pragma unroll
                for (int mt = 0; mt < 4; mt++)
                    ldsm_x4(a[mt], sb + aRowOff + mt * (16 * 128) + csel);
#pragma unroll
                for (int bt = 0; bt < 4; bt++) {
                    uint32_t bb[4];
                    ldsm_x4(bb, sb + bRowOff + bt * (16 * 128) + csel);
#pragma unroll
                    for (int mt = 0; mt < 4; mt++) {
                        mma_f16(acc[mt][bt * 2 + 0], a[mt], bb[0], bb[2]);
                        mma_f16(acc[mt][bt * 2 + 1], a[mt], bb[1], bb[3]);
                    }
                }
            }
            __syncthreads();  // all warps done with buffer g&1
            load_stage(s0 + (uint32_t)(g & 1) * STAGE, g + 2, ntiles_cta, bid,
                       stride, tid);
        }

        // Epilogue: out = exp(-(xs+ss-2*dot)) via exponent-bit trick. FMA/ALU
        // pipes only (no MUFU), registers + global only -> overlaps the two
        // in-flight cp.async stages of tile j+1.
        {
            const int g8 = lane >> 2;
            const int t4 = lane & 3;
            const int colF = nB + warpN * 64 + t4 * 4;
            float4 ss4[4];
#pragma unroll
            for (int k = 0; k < 4; k++)
                ss4[k] = *reinterpret_cast<const float4*>(g_sls + colF + 16 * k);
#pragma unroll
            for (int mt = 0; mt < 4; mt++) {
                const int r0 = mB + warpM * 64 + mt * 16 + g8;
                const float xl0 = g_xls[r0];
                const float xl1 = g_xls[r0 + 8];
                float* o0 = out + (size_t)r0 * NS + colF;
                float* o1 = o0 + (size_t)8 * NS;
#pragma unroll
                for (int k = 0; k < 4; k++) {
                    uint32_t* e0 = acc[mt][2 * k];
                    uint32_t* e1 = acc[mt][2 * k + 1];
                    float2 fa = __half22float2(*(const __half2*)&e0[0]);
                    float2 fb = __half22float2(*(const __half2*)&e1[0]);
                    float2 fc = __half22float2(*(const __half2*)&e0[1]);
                    float2 fd = __half22float2(*(const __half2*)&e1[1]);
                    float4 v0, v1;
                    v0.x = fast_exp_bits(fa.x, xl0 + ss4[k].x);
                    v0.y = fast_exp_bits(fa.y, xl0 + ss4[k].y);
                    v0.z = fast_exp_bits(fb.x, xl0 + ss4[k].z);
                    v0.w = fast_exp_bits(fb.y, xl0 + ss4[k].w);
                    v1.x = fast_exp_bits(fc.x, xl1 + ss4[k].x);
                    v1.y = fast_exp_bits(fc.y, xl1 + ss4[k].y);
                    v1.z = fast_exp_bits(fd.x, xl1 + ss4[k].z);
                    v1.w = fast_exp_bits(fd.y, xl1 + ss4[k].w);
                    *reinterpret_cast<float4*>(o0 + 16 * k) = v0;
                    *reinterpret_cast<float4*>(o1 + 16 * k) = v1;
                    e0[0] = 0u; e0[1] = 0u; e1[0] = 0u; e1[1] = 0u;
                }
            }
        }
    }
}

// ---------------------------------------------------------------------------
extern "C" void kernel_launch(void* const* d_in, const int* in_sizes, int n_in,
                              void* d_out, int out_size) {
    const float* x = (const float*)d_in[0];
    const float* s = (const float*)d_in[1];
    if (n_in >= 2 && in_sizes[0] < in_sizes[1]) {
        x = (const float*)d_in[1];
        s = (const float*)d_in[0];
    }
    float* out = (float*)d_out;

    static int nsm = 0;
    if (nsm == 0) {
        cudaFuncSetAttribute(rbf_f16_kernel,
                             cudaFuncAttributeMaxDynamicSharedMemorySize,
                             DYN_SMEM);
        cudaDeviceGetAttribute(&nsm, cudaDevAttrMultiProcessorCount, 0);
        if (nsm <= 0) nsm = 148;
    }

    prep_kernel<<<(NX + NS) / 8, 256>>>(x, s);
    rbf_f16_kernel<<<2 * nsm, 256, DYN_SMEM>>>(out);
}